// round 15
// baseline (speedup 1.0000x reference)
#include <cuda_runtime.h>
#include <cuda_bf16.h>
#include <cuda_fp16.h>
#include <math.h>
#include <stdint.h>

#define HH 128
#define WW 256
#define CC 192
#define HWP (128*256)
#define NB 2
#define LOG2E 1.4426950408889634f

// ---------------- scratch (device globals) ----------------------------------
__device__ float g_gate[NB * CC * HWP];
__device__ __half g_t[NB * 3 * CC * HWP];      // qkv pre-dw, fp16
__device__ __half g_qv[NB * 3 * CC * HWP];     // q,k,v fp16 (dw output)
__device__ __half g_xh[NB * CC * HWP];         // x fp16
__device__ __half g_ah[NB * CC * HWP];         // attn out fp16
__device__ __half g_yh[NB * CC * HWP];         // pre*gate fp16
__device__ __half g_whi[6 * CC * CC];          // [qkv|gate|pre|out]
__device__ __half g_wlo[6 * CC * CC];

// ---------------- helpers -----------------------------------------------------
__device__ __forceinline__ uint32_t smem_u32(const void* p) {
    uint32_t a;
    asm("{ .reg .u64 t; cvta.to.shared.u64 t, %1; cvt.u32.u64 %0, t; }" : "=r"(a) : "l"(p));
    return a;
}
__device__ __forceinline__ void mma16816h(float* c, const uint32_t* a,
                                          uint32_t b0, uint32_t b1)
{
    asm volatile(
        "mma.sync.aligned.m16n8k16.row.col.f32.f16.f16.f32 "
        "{%0,%1,%2,%3}, {%4,%5,%6,%7}, {%8,%9}, {%0,%1,%2,%3};\n"
        : "+f"(c[0]), "+f"(c[1]), "+f"(c[2]), "+f"(c[3])
        : "r"(a[0]), "r"(a[1]), "r"(a[2]), "r"(a[3]), "r"(b0), "r"(b1));
}
__device__ __forceinline__ void ldsm_x4(uint32_t* d, uint32_t a) {
    asm volatile("ldmatrix.sync.aligned.m8n8.x4.shared.b16 {%0,%1,%2,%3}, [%4];\n"
                 : "=r"(d[0]), "=r"(d[1]), "=r"(d[2]), "=r"(d[3]) : "r"(a));
}
__device__ __forceinline__ void ldsm_x4_t(uint32_t* d, uint32_t a) {
    asm volatile("ldmatrix.sync.aligned.m8n8.x4.trans.shared.b16 {%0,%1,%2,%3}, [%4];\n"
                 : "=r"(d[0]), "=r"(d[1]), "=r"(d[2]), "=r"(d[3]) : "r"(a));
}
__device__ __forceinline__ void ldsm_x2(uint32_t& d0, uint32_t& d1, uint32_t a) {
    asm volatile("ldmatrix.sync.aligned.m8n8.x2.shared.b16 {%0,%1}, [%2];\n"
                 : "=r"(d0), "=r"(d1) : "r"(a));
}
__device__ __forceinline__ void ldsm_x2_t(uint32_t& d0, uint32_t& d1, uint32_t a) {
    asm volatile("ldmatrix.sync.aligned.m8n8.x2.trans.shared.b16 {%0,%1}, [%2];\n"
                 : "=r"(d0), "=r"(d1) : "r"(a));
}
__device__ __forceinline__ uint32_t pack_h2(__half a, __half b) {
    __half2 t = __halves2half2(a, b);
    return *(uint32_t*)&t;
}
#define CP_CA(d, s) asm volatile("cp.async.ca.shared.global [%0], [%1], 16;\n" :: "r"(d), "l"(s))
#define CP_CG(d, s) asm volatile("cp.async.cg.shared.global [%0], [%1], 16;\n" :: "r"(d), "l"(s))
#define CP_COMMIT() asm volatile("cp.async.commit_group;\n" ::: "memory")
#define CP_WAIT2()  asm volatile("cp.async.wait_group 2;\n" ::: "memory")
#define CP_WAIT1()  asm volatile("cp.async.wait_group 1;\n" ::: "memory")
#define CP_WAIT0()  asm volatile("cp.async.wait_group 0;\n" ::: "memory")

// ---------------- fp32 -> fp16, 4/thread -------------------------------------
__global__ void __launch_bounds__(256) cvt4_kernel(
    const float* __restrict__ x, __half* __restrict__ h, int n4)
{
    int i = blockIdx.x * 256 + threadIdx.x;
    if (i < n4) {
        float4 v = ((const float4*)x)[i];
        __half hh[4] = {__float2half(v.x), __float2half(v.y),
                        __float2half(v.z), __float2half(v.w)};
        ((uint2*)h)[i] = *(uint2*)hh;
    }
}

// ---------------- fused weight splits ([qkv|gate|pre|out], fp16 hi/lo) -------
__global__ void __launch_bounds__(256) wsplit_kernel(
    const float* __restrict__ wq, const float* __restrict__ wg,
    const float* __restrict__ wp, const float* __restrict__ wo,
    __half* __restrict__ hi, __half* __restrict__ lo)
{
    const int id = blockIdx.x;
    const float* src;
    size_t dbase;
    int local;
    if (id < 108)      { src = wq; local = id;       dbase = 0; }
    else if (id < 144) { src = wg; local = id - 108; dbase = (size_t)3 * CC * CC; }
    else if (id < 180) { src = wp; local = id - 144; dbase = (size_t)4 * CC * CC; }
    else               { src = wo; local = id - 180; dbase = (size_t)5 * CC * CC; }
    const int i = local * 256 + threadIdx.x;
    float4 v = ((const float4*)src)[i];
    float vs[4] = {v.x, v.y, v.z, v.w};
    __half h[4], l[4];
#pragma unroll
    for (int j = 0; j < 4; j++) {
        h[j] = __float2half(vs[j]);
        l[j] = __float2half(vs[j] - __half2float(h[j]));
    }
    ((uint2*)(hi + dbase))[i] = *(uint2*)h;
    ((uint2*)(lo + dbase))[i] = *(uint2*)l;
}

// ---------------- fp16 W-split GEMM, BN=64 (merged qkv+gate, epi 3) ----------
#define GA_SLOT 18432
#define GB_BASE 73728
#define GB_SLOT 2304
#define GSMEM   82944

__global__ void __launch_bounds__(256, 2) gemm_fp16_kernel(
    const __half* __restrict__ Whi, const __half* __restrict__ Wlo,
    const __half* __restrict__ Xh,
    float* __restrict__ G, __half* __restrict__ Yh, int M)
{
    extern __shared__ __align__(16) char dsm[];
    const uint32_t sb = smem_u32(dsm);

    const int b  = blockIdx.z;
    const int m0 = blockIdx.y * 192;
    const int n0 = blockIdx.x * 64;
    const size_t xoff = (size_t)b * CC * HWP;

    const int tid  = threadIdx.x;
    const int lane = tid & 31;
    const int warp = tid >> 5;
    const int wm   = (warp >> 1) * 48;
    const int wn   = (warp & 1) * 32;
    const int gq   = lane >> 2;
    const int tg   = lane & 3;

    uint32_t aoff[3];
    size_t   agoff[3];
    const __half* aptr[3];
#pragma unroll
    for (int j = 0; j < 3; j++) {
        const int u = tid + 256 * j;
        const int h = (u >= 384);
        const int v = u - h * 384;
        const int r = v >> 1, c = (v & 1) * 8;
        aoff[j]  = (uint32_t)(h * 9216 + r * 48 + c * 2);
        aptr[j]  = h ? Wlo : Whi;
        agoff[j] = (size_t)(m0 + r) * CC + c;
    }
    const int doB = (tid < 128);
    const int bk = (tid & 127) >> 3, bnc = (tid & 7) * 8;
    const uint32_t boff = (uint32_t)(bk * 144 + bnc * 2);
    const size_t bgoff = xoff + (size_t)bk * HWP + n0 + bnc;

    float acc[3][4][4];
#pragma unroll
    for (int mt = 0; mt < 3; mt++)
#pragma unroll
        for (int nt = 0; nt < 4; nt++)
#pragma unroll
            for (int e = 0; e < 4; e++) acc[mt][nt][e] = 0.f;

#pragma unroll
    for (int s = 0; s < 3; s++) {
        const uint32_t as = sb + s * GA_SLOT;
        const int k0 = s * 16;
#pragma unroll
        for (int j = 0; j < 3; j++) CP_CA(as + aoff[j], aptr[j] + agoff[j] + k0);
        if (doB) CP_CG(sb + GB_BASE + s * GB_SLOT + boff, Xh + bgoff + (size_t)k0 * HWP);
        CP_COMMIT();
    }

    const int NK = CC / 16;
    for (int i = 0; i < NK; i++) {
        CP_WAIT2();
        __syncthreads();
        if (i + 3 < NK) {
            const int s = (i + 3) & 3;
            const int k0 = (i + 3) * 16;
            const uint32_t as = sb + s * GA_SLOT;
#pragma unroll
            for (int j = 0; j < 3; j++) CP_CA(as + aoff[j], aptr[j] + agoff[j] + k0);
            if (doB) CP_CG(sb + GB_BASE + s * GB_SLOT + boff, Xh + bgoff + (size_t)k0 * HWP);
        }
        CP_COMMIT();

        const uint32_t As = sb + (uint32_t)(i & 3) * GA_SLOT;
        const uint32_t Bs = sb + GB_BASE + (uint32_t)(i & 3) * GB_SLOT;

        uint32_t bf[4][2];
        {
            const uint32_t brow = (uint32_t)(lane & 15) * 144 + (uint32_t)wn * 2;
#pragma unroll
            for (int nt = 0; nt < 4; nt++)
                ldsm_x2_t(bf[nt][0], bf[nt][1], Bs + brow + nt * 16);
        }
#pragma unroll
        for (int mt = 0; mt < 3; mt++) {
            uint32_t afh[4], afl[4];
            const uint32_t arow = (uint32_t)(wm + mt * 16 + (lane & 15)) * 48
                                + (uint32_t)((lane >> 4) * 16);
            ldsm_x4(afh, As + arow);
            ldsm_x4(afl, As + 9216 + arow);
#pragma unroll
            for (int nt = 0; nt < 4; nt++) {
                mma16816h(acc[mt][nt], afh, bf[nt][0], bf[nt][1]);
                mma16816h(acc[mt][nt], afl, bf[nt][0], bf[nt][1]);
            }
        }
    }

    const size_t yoff = (size_t)b * M * HWP;
    const size_t goff = (size_t)b * CC * HWP;
    const int gateBlk = (m0 == 576);
#pragma unroll
    for (int mt = 0; mt < 3; mt++) {
        const int r0 = m0 + wm + mt * 16 + gq;
        const int r1 = r0 + 8;
#pragma unroll
        for (int nt = 0; nt < 4; nt++) {
            const int c = n0 + wn + nt * 8 + 2 * tg;
            float v00 = acc[mt][nt][0], v01 = acc[mt][nt][1];
            float v10 = acc[mt][nt][2], v11 = acc[mt][nt][3];
            if (gateBlk) {
                v00 = v00 / (1.f + __expf(-v00));
                v01 = v01 / (1.f + __expf(-v01));
                v10 = v10 / (1.f + __expf(-v10));
                v11 = v11 / (1.f + __expf(-v11));
                *(float2*)(G + goff + (size_t)(r0 - 576) * HWP + c) = make_float2(v00, v01);
                *(float2*)(G + goff + (size_t)(r1 - 576) * HWP + c) = make_float2(v10, v11);
            } else {
                *(uint32_t*)(Yh + yoff + (size_t)r0 * HWP + c) =
                    pack_h2(__float2half(v00), __float2half(v01));
                *(uint32_t*)(Yh + yoff + (size_t)r1 * HWP + c) =
                    pack_h2(__float2half(v10), __float2half(v11));
            }
        }
    }
}

// ---------------- BN=32 GEMM (pre / out): better wave quantization -----------
// tile 192m x 32n x 16k; 8 warps (4m x 2n of 16); 12 mma/iter/warp.
// B slot: 16 x 40 halfs (80B row; mod-128 offsets distinct -> conflict-free).
#define GB32_SLOT 2560
#define GSMEM32   83968    // 4*GA_SLOT + 4*GB32_SLOT

__global__ void __launch_bounds__(256, 2) gemm32_kernel(
    const __half* __restrict__ Whi, const __half* __restrict__ Wlo,
    const __half* __restrict__ Xh,
    float* __restrict__ Yf, const float* __restrict__ G,
    __half* __restrict__ Yh, int epi)
{
    extern __shared__ __align__(16) char dsm[];
    const uint32_t sb = smem_u32(dsm);

    const int b  = blockIdx.z;
    const int n0 = blockIdx.x * 32;
    const size_t xoff = (size_t)b * CC * HWP;

    const int tid  = threadIdx.x;
    const int lane = tid & 31;
    const int warp = tid >> 5;
    const int wm   = (warp >> 1) * 48;
    const int wn   = (warp & 1) * 16;
    const int gq   = lane >> 2;
    const int tg   = lane & 3;

    uint32_t aoff[3];
    size_t   agoff[3];
    const __half* aptr[3];
#pragma unroll
    for (int j = 0; j < 3; j++) {
        const int u = tid + 256 * j;
        const int h = (u >= 384);
        const int v = u - h * 384;
        const int r = v >> 1, c = (v & 1) * 8;
        aoff[j]  = (uint32_t)(h * 9216 + r * 48 + c * 2);
        aptr[j]  = h ? Wlo : Whi;
        agoff[j] = (size_t)r * CC + c;
    }
    const int doB = (tid < 64);
    const int bk = tid >> 2, bnc = (tid & 3) * 8;
    const uint32_t boff = (uint32_t)(bk * 80 + bnc * 2);
    const size_t bgoff = xoff + (size_t)bk * HWP + n0 + bnc;

    float acc[3][2][4];
#pragma unroll
    for (int mt = 0; mt < 3; mt++)
#pragma unroll
        for (int nt = 0; nt < 2; nt++)
#pragma unroll
            for (int e = 0; e < 4; e++) acc[mt][nt][e] = 0.f;

#pragma unroll
    for (int s = 0; s < 3; s++) {
        const uint32_t as = sb + s * GA_SLOT;
        const int k0 = s * 16;
#pragma unroll
        for (int j = 0; j < 3; j++) CP_CA(as + aoff[j], aptr[j] + agoff[j] + k0);
        if (doB) CP_CG(sb + GB_BASE + s * GB32_SLOT + boff, Xh + bgoff + (size_t)k0 * HWP);
        CP_COMMIT();
    }

    const int NK = CC / 16;
    for (int i = 0; i < NK; i++) {
        CP_WAIT2();
        __syncthreads();
        if (i + 3 < NK) {
            const int s = (i + 3) & 3;
            const int k0 = (i + 3) * 16;
            const uint32_t as = sb + s * GA_SLOT;
#pragma unroll
            for (int j = 0; j < 3; j++) CP_CA(as + aoff[j], aptr[j] + agoff[j] + k0);
            if (doB) CP_CG(sb + GB_BASE + s * GB32_SLOT + boff, Xh + bgoff + (size_t)k0 * HWP);
        }
        CP_COMMIT();

        const uint32_t As = sb + (uint32_t)(i & 3) * GA_SLOT;
        const uint32_t Bs = sb + GB_BASE + (uint32_t)(i & 3) * GB32_SLOT;

        uint32_t bf[2][2];
        {
            const uint32_t brow = (uint32_t)(lane & 15) * 80 + (uint32_t)wn * 2;
#pragma unroll
            for (int nt = 0; nt < 2; nt++)
                ldsm_x2_t(bf[nt][0], bf[nt][1], Bs + brow + nt * 16);
        }
#pragma unroll
        for (int mt = 0; mt < 3; mt++) {
            uint32_t afh[4], afl[4];
            const uint32_t arow = (uint32_t)(wm + mt * 16 + (lane & 15)) * 48
                                + (uint32_t)((lane >> 4) * 16);
            ldsm_x4(afh, As + arow);
            ldsm_x4(afl, As + 9216 + arow);
#pragma unroll
            for (int nt = 0; nt < 2; nt++) {
                mma16816h(acc[mt][nt], afh, bf[nt][0], bf[nt][1]);
                mma16816h(acc[mt][nt], afl, bf[nt][0], bf[nt][1]);
            }
        }
    }

    const size_t yoff = (size_t)b * CC * HWP;
#pragma unroll
    for (int mt = 0; mt < 3; mt++) {
        const int r0 = wm + mt * 16 + gq;
        const int r1 = r0 + 8;
#pragma unroll
        for (int nt = 0; nt < 2; nt++) {
            const int c = n0 + wn + nt * 8 + 2 * tg;
            float v00 = acc[mt][nt][0], v01 = acc[mt][nt][1];
            float v10 = acc[mt][nt][2], v11 = acc[mt][nt][3];
            if (epi == 2) {
                float2 g0 = *(const float2*)(G + yoff + (size_t)r0 * HWP + c);
                float2 g1 = *(const float2*)(G + yoff + (size_t)r1 * HWP + c);
                v00 *= g0.x; v01 *= g0.y; v10 *= g1.x; v11 *= g1.y;
                *(uint32_t*)(Yh + yoff + (size_t)r0 * HWP + c) =
                    pack_h2(__float2half(v00), __float2half(v01));
                *(uint32_t*)(Yh + yoff + (size_t)r1 * HWP + c) =
                    pack_h2(__float2half(v10), __float2half(v11));
            } else {
                *(float2*)(Yf + yoff + (size_t)r0 * HWP + c) = make_float2(v00, v01);
                *(float2*)(Yf + yoff + (size_t)r1 * HWP + c) = make_float2(v10, v11);
            }
        }
    }
}

// ---------------- depthwise 3x3, 4x8 patch/thread, fp16 in/out ---------------
__global__ void __launch_bounds__(256) dw_kernel(
    const __half* __restrict__ t, const float* __restrict__ wd,
    __half* __restrict__ oh)
{
    const int cb = blockIdx.y;
    const int c  = cb % (3 * CC);
    const int tx = threadIdx.x;
    const int x  = (tx & 31) * 8;
    const int yq = blockIdx.x * 32 + (tx >> 5) * 4;
    const __half* base = t + (size_t)cb * HWP;

    float w[9];
#pragma unroll
    for (int i = 0; i < 9; i++) w[i] = wd[c * 9 + i];

    float acc[4][8];
#pragma unroll
    for (int o = 0; o < 4; o++)
#pragma unroll
        for (int i = 0; i < 8; i++) acc[o][i] = 0.f;

#pragma unroll
    for (int ry = -1; ry <= 4; ry++) {
        const int yy = yq + ry;
        if (yy < 0 || yy >= HH) continue;
        const __half* r = base + yy * WW + x;
        uint4 u = *(const uint4*)r;
        __half hv[8];
        *(uint4*)hv = u;
        float v[10];
        v[0] = (x > 0) ? __half2float(r[-1]) : 0.f;
#pragma unroll
        for (int i = 0; i < 8; i++) v[i + 1] = __half2float(hv[i]);
        v[9] = (x < 248) ? __half2float(r[8]) : 0.f;
#pragma unroll
        for (int o = 0; o < 4; o++) {
            const int d = ry - o;
            if (d < -1 || d > 1) continue;
            const int wr = (d + 1) * 3;
#pragma unroll
            for (int i = 0; i < 8; i++)
                acc[o][i] = fmaf(w[wr], v[i],
                            fmaf(w[wr + 1], v[i + 1],
                            fmaf(w[wr + 2], v[i + 2], acc[o][i])));
        }
    }
#pragma unroll
    for (int o = 0; o < 4; o++) {
        __half h[8];
#pragma unroll
        for (int i = 0; i < 8; i++) h[i] = __float2half(acc[o][i]);
        *(uint4*)(oh + (size_t)cb * HWP + (yq + o) * WW + x) = *(uint4*)h;
    }
}

// ---------------- attention (R11: 256 thr, 2 CTA/SM, cp.async dbuf) ----------
__global__ void __launch_bounds__(256, 2) attn_mma_kernel(
    const __half* __restrict__ qv, const float* __restrict__ rpb,
    __half* __restrict__ oa)
{
    __shared__ float bsh[512];
    __shared__ __align__(16) __half KV[2][2][32][72];
    __shared__ __align__(16) float stage[128 * 33];

    const int row = blockIdx.x;
    const int head = blockIdx.y % 6, qh = blockIdx.y / 6;
    const int b = blockIdx.z;
    const int tid = threadIdx.x, lane = tid & 31, warp = tid >> 5;
    const int gq = lane >> 2, tg = lane & 3;
    const size_t base = (((size_t)b * (3 * CC) + head * 32) * HH + row) * WW;
    const size_t koff = (size_t)CC * HWP;
    const float scale2 = 0.17677669529663687f * LOG2E;

    const int cd = tid >> 3, cj = (tid & 7) * 8;
    {
        const size_t kb = base + koff + (size_t)cd * HWP + 0 + cj;
        CP_CG(smem_u32(&KV[0][0][cd][cj]), qv + kb);
        CP_CG(smem_u32(&KV[0][1][cd][cj]), qv + kb + koff);
        CP_COMMIT();
    }

    for (int i = tid; i < 511; i += 256) bsh[i] = rpb[i * 6 + head] * LOG2E;

    uint32_t qf[2][4];
    {
        __half* Qst = (__half*)stage;
        const int d = tid >> 3, q16 = (tid & 7) * 16;
        const size_t go = base + (size_t)d * HWP + qh * 128 + q16;
        uint4 v0 = *(const uint4*)(qv + go);
        uint4 v1 = *(const uint4*)(qv + go + 8);
        *(uint4*)&Qst[d * 136 + q16] = v0;
        *(uint4*)&Qst[d * 136 + q16 + 8] = v1;
        __syncthreads();
        const int lrow = ((lane >> 4) & 1) * 8 + (lane & 7);
        const int lcol = warp * 16 + ((lane >> 3) & 1) * 8;
#pragma unroll
        for (int ks = 0; ks < 2; ks++)
            ldsm_x4_t(qf[ks], smem_u32(&Qst[(ks * 16 + lrow) * 136 + lcol]));
        __syncthreads();
    }

    float m2[2] = {-1e30f, -1e30f}, l2[2] = {0.f, 0.f};
    float o[4][4];
#pragma unroll
    for (int nt = 0; nt < 4; nt++)
#pragma unroll
        for (int e = 0; e < 4; e++) o[nt][e] = 0.f;

    for (int ic = 0; ic < 4; ic++) {
        const int jt = ic * 64;
        const int sl = ic & 1;
        if (ic + 1 < 4) {
            const size_t kb = base + koff + (size_t)cd * HWP + jt + 64 + cj;
            CP_CG(smem_u32(&KV[sl ^ 1][0][cd][cj]), qv + kb);
            CP_CG(smem_u32(&KV[sl ^ 1][1][cd][cj]), qv + kb + koff);
            CP_COMMIT();
            CP_WAIT1();
        } else {
            CP_WAIT0();
        }
        __syncthreads();

        float s[8][4];
#pragma unroll
        for (int nt = 0; nt < 8; nt++)
#pragma unroll
            for (int e = 0; e < 4; e++) s[nt][e] = 0.f;
        const int krow = lane & 15;
#pragma unroll
        for (int ks = 0; ks < 2; ks++) {
            const uint32_t kb0 = smem_u32(&KV[sl][0][ks * 16 + krow][0]);
#pragma unroll
            for (int nt = 0; nt < 8; nt++) {
                uint32_t h0, h1;
                ldsm_x2_t(h0, h1, kb0 + nt * 16);
                mma16816h(s[nt], qf[ks], h0, h1);
            }
        }

        float mx[2] = {m2[0], m2[1]};
        const int i0 = qh * 128 + warp * 16 + gq;
#pragma unroll
        for (int nt = 0; nt < 8; nt++) {
            const int jb = jt + nt * 8 + 2 * tg;
#pragma unroll
            for (int e = 0; e < 4; e++) {
                const int i = i0 + (e >> 1) * 8;
                const int j = jb + (e & 1);
                const float t = fmaf(s[nt][e], scale2, bsh[i - j + 255]);
                s[nt][e] = t;
                mx[e >> 1] = fmaxf(mx[e >> 1], t);
            }
        }
#pragma unroll
        for (int slx = 0; slx < 2; slx++) {
            float v = mx[slx];
            v = fmaxf(v, __shfl_xor_sync(0xFFFFFFFFu, v, 1));
            v = fmaxf(v, __shfl_xor_sync(0xFFFFFFFFu, v, 2));
            mx[slx] = v;
        }
        float cf[2];
#pragma unroll
        for (int slx = 0; slx < 2; slx++) {
            cf[slx] = exp2f(m2[slx] - mx[slx]);
            m2[slx] = mx[slx];
            l2[slx] *= cf[slx];
        }
#pragma unroll
        for (int nt = 0; nt < 4; nt++)
#pragma unroll
            for (int e = 0; e < 4; e++) o[nt][e] *= cf[e >> 1];

        float rs[2] = {0.f, 0.f};
#pragma unroll
        for (int kp = 0; kp < 4; kp++) {
            uint32_t pf[4];
#pragma unroll
            for (int h2 = 0; h2 < 2; h2++) {
                const int nt = 2 * kp + h2;
                float p0 = exp2f(s[nt][0] - m2[0]);
                float p1 = exp2f(s[nt][1] - m2[0]);
                float p2 = exp2f(s[nt][2] - m2[1]);
                float p3 = exp2f(s[nt][3] - m2[1]);
                rs[0] += p0 + p1;
                rs[1] += p2 + p3;
                pf[h2 * 2 + 0] = pack_h2(__float2half(p0), __float2half(p1));
                pf[h2 * 2 + 1] = pack_h2(__float2half(p2), __float2half(p3));
            }
            const int vr = lane & 7, vk = kp * 16 + ((lane >> 3) & 1) * 8;
#pragma unroll
            for (int ntv = 0; ntv < 4; ntv++) {
                uint32_t v0, v1;
                ldsm_x2(v0, v1, smem_u32(&KV[sl][1][ntv * 8 + vr][vk]));
                mma16816h(o[ntv], pf, v0, v1);
            }
        }
#pragma unroll
        for (int slx = 0; slx < 2; slx++) {
            float r = rs[slx];
            r += __shfl_xor_sync(0xFFFFFFFFu, r, 1);
            r += __shfl_xor_sync(0xFFFFFFFFu, r, 2);
            l2[slx] += r;
        }
        __syncthreads();
    }

    const float inv0 = 1.f / l2[0], inv1 = 1.f / l2[1];
#pragma unroll
    for (int nt = 0; nt < 4; nt++) {
        const int c = nt * 8 + 2 * tg;
#pragma unroll
        for (int e = 0; e < 4; e++) {
            const int rr = warp * 16 + gq + (e >> 1) * 8;
            stage[rr * 33 + c + (e & 1)] = o[nt][e] * ((e >> 1) ? inv1 : inv0);
        }
    }
    __syncthreads();
    const size_t obase = (((size_t)b * CC + head * 32) * HH + row) * WW + qh * 128;
    const int q = tid & 127, db = (tid >> 7) * 16;
#pragma unroll
    for (int dd = 0; dd < 16; dd++) {
        const int d = db + dd;
        oa[obase + (size_t)d * HWP + q] = __float2half(stage[q * 33 + d]);
    }
}

// ---------------- launch ------------------------------------------------------
extern "C" void kernel_launch(void* const* d_in, const int* in_sizes, int n_in,
                              void* d_out, int out_size)
{
    const float* x       = (const float*)d_in[0];
    const float* rpb     = (const float*)d_in[1];
    const float* w_qkv   = (const float*)d_in[2];
    const float* w_depth = (const float*)d_in[3];
    const float* w_pre   = (const float*)d_in[4];
    const float* w_out   = (const float*)d_in[5];
    const float* w_gate  = (const float*)d_in[6];
    float* out = (float*)d_out;
    (void)in_sizes; (void)n_in; (void)out_size;

    float* gate;
    __half *th, *qv, *xh, *ah, *yh, *whi, *wlo;
    cudaGetSymbolAddress((void**)&gate, g_gate);
    cudaGetSymbolAddress((void**)&th,   g_t);
    cudaGetSymbolAddress((void**)&qv,   g_qv);
    cudaGetSymbolAddress((void**)&xh,   g_xh);
    cudaGetSymbolAddress((void**)&ah,   g_ah);
    cudaGetSymbolAddress((void**)&yh,   g_yh);
    cudaGetSymbolAddress((void**)&whi,  g_whi);
    cudaGetSymbolAddress((void**)&wlo,  g_wlo);

    cudaFuncSetAttribute(gemm_fp16_kernel,
                         cudaFuncAttributeMaxDynamicSharedMemorySize, GSMEM);
    cudaFuncSetAttribute(gemm32_kernel,
                         cudaFuncAttributeMaxDynamicSharedMemorySize, GSMEM32);

    const int WS = CC * CC;
    const int nx = NB * CC * HWP;
    cvt4_kernel<<<(nx / 4 + 255) / 256, 256>>>(x, xh, nx / 4);
    wsplit_kernel<<<216, 256>>>(w_qkv, w_gate, w_pre, w_out, whi, wlo);

    const dim3 gMerged(HWP / 64, 4, NB);     // M=768: qkv(576 -> fp16 t) + gate(192 -> silu f32)
    const dim3 g32(HWP / 32, 1, NB);         // BN=32: 2048 blocks -> 7 waves @98.8%

    // [t | gate] = [W_qkv; W_gate] @ x
    gemm_fp16_kernel<<<gMerged, 256, GSMEM>>>(whi, wlo, xh, gate, th, 3 * CC);
    // q,k,v = depthwise3x3(t) -> fp16
    dw_kernel<<<dim3(HH / 32, NB * 3 * CC), 256>>>(th, w_depth, qv);
    // attention -> fp16
    attn_mma_kernel<<<dim3(HH, 12, NB), 256>>>(qv, rpb, ah);
    // y = (W_pre @ attn) * gate -> fp16
    gemm32_kernel<<<g32, 256, GSMEM32>>>(whi + 4 * WS, wlo + 4 * WS, ah,
                                         nullptr, gate, yh, 2);
    // out = W_out @ y
    gemm32_kernel<<<g32, 256, GSMEM32>>>(whi + 5 * WS, wlo + 5 * WS, yh,
                                         out, nullptr, nullptr, 0);
}

// round 16
// speedup vs baseline: 1.1708x; 1.1708x over previous
#include <cuda_runtime.h>
#include <cuda_bf16.h>
#include <cuda_fp16.h>
#include <math.h>
#include <stdint.h>

#define HH 128
#define WW 256
#define CC 192
#define HWP (128*256)
#define NB 2
#define LOG2E 1.4426950408889634f

// ---------------- scratch (device globals) ----------------------------------
__device__ float g_gate[NB * CC * HWP];
__device__ __half g_t[NB * 3 * CC * HWP];      // qkv pre-dw, fp16
__device__ __half g_qv[NB * 3 * CC * HWP];     // q,k,v fp16 (dw output)
__device__ __half g_xh[NB * CC * HWP];         // x fp16
__device__ __half g_ah[NB * CC * HWP];         // attn out fp16
__device__ __half g_yh[NB * CC * HWP];         // pre*gate fp16
__device__ __half g_whi[6 * CC * CC];          // [qkv|gate|pre|out]
__device__ __half g_wlo[6 * CC * CC];

// ---------------- helpers -----------------------------------------------------
__device__ __forceinline__ uint32_t smem_u32(const void* p) {
    uint32_t a;
    asm("{ .reg .u64 t; cvta.to.shared.u64 t, %1; cvt.u32.u64 %0, t; }" : "=r"(a) : "l"(p));
    return a;
}
__device__ __forceinline__ void mma16816h(float* c, const uint32_t* a,
                                          uint32_t b0, uint32_t b1)
{
    asm volatile(
        "mma.sync.aligned.m16n8k16.row.col.f32.f16.f16.f32 "
        "{%0,%1,%2,%3}, {%4,%5,%6,%7}, {%8,%9}, {%0,%1,%2,%3};\n"
        : "+f"(c[0]), "+f"(c[1]), "+f"(c[2]), "+f"(c[3])
        : "r"(a[0]), "r"(a[1]), "r"(a[2]), "r"(a[3]), "r"(b0), "r"(b1));
}
__device__ __forceinline__ void ldsm_x4(uint32_t* d, uint32_t a) {
    asm volatile("ldmatrix.sync.aligned.m8n8.x4.shared.b16 {%0,%1,%2,%3}, [%4];\n"
                 : "=r"(d[0]), "=r"(d[1]), "=r"(d[2]), "=r"(d[3]) : "r"(a));
}
__device__ __forceinline__ void ldsm_x4_t(uint32_t* d, uint32_t a) {
    asm volatile("ldmatrix.sync.aligned.m8n8.x4.trans.shared.b16 {%0,%1,%2,%3}, [%4];\n"
                 : "=r"(d[0]), "=r"(d[1]), "=r"(d[2]), "=r"(d[3]) : "r"(a));
}
__device__ __forceinline__ void ldsm_x2(uint32_t& d0, uint32_t& d1, uint32_t a) {
    asm volatile("ldmatrix.sync.aligned.m8n8.x2.shared.b16 {%0,%1}, [%2];\n"
                 : "=r"(d0), "=r"(d1) : "r"(a));
}
__device__ __forceinline__ void ldsm_x2_t(uint32_t& d0, uint32_t& d1, uint32_t a) {
    asm volatile("ldmatrix.sync.aligned.m8n8.x2.trans.shared.b16 {%0,%1}, [%2];\n"
                 : "=r"(d0), "=r"(d1) : "r"(a));
}
__device__ __forceinline__ uint32_t pack_h2(__half a, __half b) {
    __half2 t = __halves2half2(a, b);
    return *(uint32_t*)&t;
}
#define CP_CA(d, s) asm volatile("cp.async.ca.shared.global [%0], [%1], 16;\n" :: "r"(d), "l"(s))
#define CP_CG(d, s) asm volatile("cp.async.cg.shared.global [%0], [%1], 16;\n" :: "r"(d), "l"(s))
#define CP_COMMIT() asm volatile("cp.async.commit_group;\n" ::: "memory")
#define CP_WAIT2()  asm volatile("cp.async.wait_group 2;\n" ::: "memory")
#define CP_WAIT1()  asm volatile("cp.async.wait_group 1;\n" ::: "memory")
#define CP_WAIT0()  asm volatile("cp.async.wait_group 0;\n" ::: "memory")

// ---------------- fp32 -> fp16, 4/thread -------------------------------------
__global__ void __launch_bounds__(256) cvt4_kernel(
    const float* __restrict__ x, __half* __restrict__ h, int n4)
{
    int i = blockIdx.x * 256 + threadIdx.x;
    if (i < n4) {
        float4 v = ((const float4*)x)[i];
        __half hh[4] = {__float2half(v.x), __float2half(v.y),
                        __float2half(v.z), __float2half(v.w)};
        ((uint2*)h)[i] = *(uint2*)hh;
    }
}

// ---------------- fused weight splits ([qkv|gate|pre|out], fp16 hi/lo) -------
__global__ void __launch_bounds__(256) wsplit_kernel(
    const float* __restrict__ wq, const float* __restrict__ wg,
    const float* __restrict__ wp, const float* __restrict__ wo,
    __half* __restrict__ hi, __half* __restrict__ lo)
{
    const int id = blockIdx.x;
    const float* src;
    size_t dbase;
    int local;
    if (id < 108)      { src = wq; local = id;       dbase = 0; }
    else if (id < 144) { src = wg; local = id - 108; dbase = (size_t)3 * CC * CC; }
    else if (id < 180) { src = wp; local = id - 144; dbase = (size_t)4 * CC * CC; }
    else               { src = wo; local = id - 180; dbase = (size_t)5 * CC * CC; }
    const int i = local * 256 + threadIdx.x;
    float4 v = ((const float4*)src)[i];
    float vs[4] = {v.x, v.y, v.z, v.w};
    __half h[4], l[4];
#pragma unroll
    for (int j = 0; j < 4; j++) {
        h[j] = __float2half(vs[j]);
        l[j] = __float2half(vs[j] - __half2float(h[j]));
    }
    ((uint2*)(hi + dbase))[i] = *(uint2*)h;
    ((uint2*)(lo + dbase))[i] = *(uint2*)l;
}

// ---------------- A-resident fp16 GEMM ---------------------------------------
// BM=96 (full-K A in smem, loaded once), BN=64, NSUP=4 n-tiles per block.
// 8 warps = 2m(48) x 4n(16); 12 mma/iter/warp; B via 4-slot cp.async ring.
// A smem: [half][96][200 halfs] (400B rows: conflict-free ldsm.x4)
// epi: 0 f32 out; 2 (*G f32)->fp16; 3 merged: m0<576 -> fp16 Yh, else silu->f32 G.
#define AR_HALF 38400                    // 96*400 bytes
#define AR_BYTES 76800
#define BR_SLOT 2304                     // 16 x 72 halfs
#define GSMEM (AR_BYTES + 4 * BR_SLOT)   // 86016
#define NSUP 4

__global__ void __launch_bounds__(256, 2) gemm_ar_kernel(
    const __half* __restrict__ Whi, const __half* __restrict__ Wlo,
    const __half* __restrict__ Xh,
    float* __restrict__ Yf, float* __restrict__ G,
    __half* __restrict__ Yh, int M, int epi)
{
    extern __shared__ __align__(16) char dsm[];
    const uint32_t sb = smem_u32(dsm);

    const int b  = blockIdx.z;
    const int m0 = blockIdx.y * 96;
    const int n0b = blockIdx.x * (64 * NSUP);
    const size_t xoff = (size_t)b * CC * HWP;

    const int tid  = threadIdx.x;
    const int lane = tid & 31;
    const int warp = tid >> 5;
    const int wm   = (warp >> 2) * 48;
    const int wn   = (warp & 3) * 16;
    const int gq   = lane >> 2;
    const int tg   = lane & 3;

    // B loader mapping (128 loader threads, 1x16B each)
    const int doB = (tid < 128);
    const int bk = (tid & 127) >> 3, bnc = (tid & 7) * 8;
    const uint32_t boff = (uint32_t)(bk * 144 + bnc * 2);

    // ---- one-time A load (96 x 192 x 2 halves) + B prologue ----
    for (int u = tid; u < 4608; u += 256) {
        const int h = u >> 11 >= 1 ? (u >= 2304) : 0;   // u/2304
        const int hh = (u >= 2304);
        const int v = u - hh * 2304;
        const int r = v / 24, c = v - r * 24;
        CP_CA(sb + hh * AR_HALF + (uint32_t)(r * 400 + c * 16),
              (hh ? Wlo : Whi) + (size_t)(m0 + r) * CC + c * 8);
        (void)h;
    }
    const int TOT = NSUP * 12;
    // B slot for g: tile = g/12, k = g%12
    if (doB) CP_CG(sb + AR_BYTES + 0 * BR_SLOT + boff,
                   Xh + xoff + (size_t)bk * HWP + n0b + bnc);
    CP_COMMIT();                          // group: A + B(g=0)
#pragma unroll
    for (int s = 1; s < 3; s++) {
        if (doB) CP_CG(sb + AR_BYTES + s * BR_SLOT + boff,
                       Xh + xoff + (size_t)(s * 16 + bk) * HWP + n0b + bnc);
        CP_COMMIT();
    }

    float acc[3][2][4];
#pragma unroll
    for (int mt = 0; mt < 3; mt++)
#pragma unroll
        for (int nt = 0; nt < 2; nt++)
#pragma unroll
            for (int e = 0; e < 4; e++) acc[mt][nt][e] = 0.f;

    const size_t yoff = (size_t)b * M * HWP;
    const size_t goff = (size_t)b * CC * HWP;
    const int gateBlk = (epi == 3 && m0 >= 576);

    int tile = 0, k = 0;
    int ptile = 0, pk = 3;                // prefetch cursor = g+3
    for (int g = 0; g < TOT; g++) {
        CP_WAIT2();
        __syncthreads();
        if (g + 3 < TOT) {
            if (doB) CP_CG(sb + AR_BYTES + (uint32_t)((g + 3) & 3) * BR_SLOT + boff,
                           Xh + xoff + (size_t)(pk * 16 + bk) * HWP
                              + n0b + ptile * 64 + bnc);
            if (++pk == 12) { pk = 0; ptile++; }
        }
        CP_COMMIT();

        const uint32_t Bs = sb + AR_BYTES + (uint32_t)(g & 3) * BR_SLOT;
        uint32_t bf[2][2];
        {
            const uint32_t brow = (uint32_t)(lane & 15) * 144 + (uint32_t)wn * 2;
#pragma unroll
            for (int nt = 0; nt < 2; nt++)
                ldsm_x2_t(bf[nt][0], bf[nt][1], Bs + brow + nt * 16);
        }
#pragma unroll
        for (int mt = 0; mt < 3; mt++) {
            uint32_t afh[4], afl[4];
            const uint32_t arow = (uint32_t)(wm + mt * 16 + (lane & 15)) * 400
                                + (uint32_t)(k * 32 + (lane >> 4) * 16);
            ldsm_x4(afh, sb + arow);
            ldsm_x4(afl, sb + AR_HALF + arow);
#pragma unroll
            for (int nt = 0; nt < 2; nt++) {
                mma16816h(acc[mt][nt], afh, bf[nt][0], bf[nt][1]);
                mma16816h(acc[mt][nt], afl, bf[nt][0], bf[nt][1]);
            }
        }

        if (++k == 12) {
            // ---- epilogue for this n-tile ----
            const int n0 = n0b + tile * 64;
#pragma unroll
            for (int mt = 0; mt < 3; mt++) {
                const int r0 = m0 + wm + mt * 16 + gq;
                const int r1 = r0 + 8;
#pragma unroll
                for (int nt = 0; nt < 2; nt++) {
                    const int c = n0 + wn + nt * 8 + 2 * tg;
                    float v00 = acc[mt][nt][0], v01 = acc[mt][nt][1];
                    float v10 = acc[mt][nt][2], v11 = acc[mt][nt][3];
                    if (gateBlk) {
                        v00 = v00 / (1.f + __expf(-v00));
                        v01 = v01 / (1.f + __expf(-v01));
                        v10 = v10 / (1.f + __expf(-v10));
                        v11 = v11 / (1.f + __expf(-v11));
                        *(float2*)(G + goff + (size_t)(r0 - 576) * HWP + c) =
                            make_float2(v00, v01);
                        *(float2*)(G + goff + (size_t)(r1 - 576) * HWP + c) =
                            make_float2(v10, v11);
                    } else if (epi == 3) {
                        *(uint32_t*)(Yh + yoff + (size_t)r0 * HWP + c) =
                            pack_h2(__float2half(v00), __float2half(v01));
                        *(uint32_t*)(Yh + yoff + (size_t)r1 * HWP + c) =
                            pack_h2(__float2half(v10), __float2half(v11));
                    } else if (epi == 2) {
                        float2 g0 = *(const float2*)(G + goff + (size_t)r0 * HWP + c);
                        float2 g1 = *(const float2*)(G + goff + (size_t)r1 * HWP + c);
                        v00 *= g0.x; v01 *= g0.y; v10 *= g1.x; v11 *= g1.y;
                        *(uint32_t*)(Yh + yoff + (size_t)r0 * HWP + c) =
                            pack_h2(__float2half(v00), __float2half(v01));
                        *(uint32_t*)(Yh + yoff + (size_t)r1 * HWP + c) =
                            pack_h2(__float2half(v10), __float2half(v11));
                    } else {
                        *(float2*)(Yf + yoff + (size_t)r0 * HWP + c) =
                            make_float2(v00, v01);
                        *(float2*)(Yf + yoff + (size_t)r1 * HWP + c) =
                            make_float2(v10, v11);
                    }
                    acc[mt][nt][0] = 0.f; acc[mt][nt][1] = 0.f;
                    acc[mt][nt][2] = 0.f; acc[mt][nt][3] = 0.f;
                }
            }
            k = 0;
            tile++;
        }
    }
}

// ---------------- depthwise 3x3, 4x8 patch/thread, fp16 in/out ---------------
__global__ void __launch_bounds__(256) dw_kernel(
    const __half* __restrict__ t, const float* __restrict__ wd,
    __half* __restrict__ oh)
{
    const int cb = blockIdx.y;
    const int c  = cb % (3 * CC);
    const int tx = threadIdx.x;
    const int x  = (tx & 31) * 8;
    const int yq = blockIdx.x * 32 + (tx >> 5) * 4;
    const __half* base = t + (size_t)cb * HWP;

    float w[9];
#pragma unroll
    for (int i = 0; i < 9; i++) w[i] = wd[c * 9 + i];

    float acc[4][8];
#pragma unroll
    for (int o = 0; o < 4; o++)
#pragma unroll
        for (int i = 0; i < 8; i++) acc[o][i] = 0.f;

#pragma unroll
    for (int ry = -1; ry <= 4; ry++) {
        const int yy = yq + ry;
        if (yy < 0 || yy >= HH) continue;
        const __half* r = base + yy * WW + x;
        uint4 u = *(const uint4*)r;
        __half hv[8];
        *(uint4*)hv = u;
        float v[10];
        v[0] = (x > 0) ? __half2float(r[-1]) : 0.f;
#pragma unroll
        for (int i = 0; i < 8; i++) v[i + 1] = __half2float(hv[i]);
        v[9] = (x < 248) ? __half2float(r[8]) : 0.f;
#pragma unroll
        for (int o = 0; o < 4; o++) {
            const int d = ry - o;
            if (d < -1 || d > 1) continue;
            const int wr = (d + 1) * 3;
#pragma unroll
            for (int i = 0; i < 8; i++)
                acc[o][i] = fmaf(w[wr], v[i],
                            fmaf(w[wr + 1], v[i + 1],
                            fmaf(w[wr + 2], v[i + 2], acc[o][i])));
        }
    }
#pragma unroll
    for (int o = 0; o < 4; o++) {
        __half h[8];
#pragma unroll
        for (int i = 0; i < 8; i++) h[i] = __float2half(acc[o][i]);
        *(uint4*)(oh + (size_t)cb * HWP + (yq + o) * WW + x) = *(uint4*)h;
    }
}

// ---------------- attention (R11: 256 thr, 2 CTA/SM, cp.async dbuf) ----------
__global__ void __launch_bounds__(256, 2) attn_mma_kernel(
    const __half* __restrict__ qv, const float* __restrict__ rpb,
    __half* __restrict__ oa)
{
    __shared__ float bsh[512];
    __shared__ __align__(16) __half KV[2][2][32][72];
    __shared__ __align__(16) float stage[128 * 33];

    const int row = blockIdx.x;
    const int head = blockIdx.y % 6, qh = blockIdx.y / 6;
    const int b = blockIdx.z;
    const int tid = threadIdx.x, lane = tid & 31, warp = tid >> 5;
    const int gq = lane >> 2, tg = lane & 3;
    const size_t base = (((size_t)b * (3 * CC) + head * 32) * HH + row) * WW;
    const size_t koff = (size_t)CC * HWP;
    const float scale2 = 0.17677669529663687f * LOG2E;

    const int cd = tid >> 3, cj = (tid & 7) * 8;
    {
        const size_t kb = base + koff + (size_t)cd * HWP + 0 + cj;
        CP_CG(smem_u32(&KV[0][0][cd][cj]), qv + kb);
        CP_CG(smem_u32(&KV[0][1][cd][cj]), qv + kb + koff);
        CP_COMMIT();
    }

    for (int i = tid; i < 511; i += 256) bsh[i] = rpb[i * 6 + head] * LOG2E;

    uint32_t qf[2][4];
    {
        __half* Qst = (__half*)stage;
        const int d = tid >> 3, q16 = (tid & 7) * 16;
        const size_t go = base + (size_t)d * HWP + qh * 128 + q16;
        uint4 v0 = *(const uint4*)(qv + go);
        uint4 v1 = *(const uint4*)(qv + go + 8);
        *(uint4*)&Qst[d * 136 + q16] = v0;
        *(uint4*)&Qst[d * 136 + q16 + 8] = v1;
        __syncthreads();
        const int lrow = ((lane >> 4) & 1) * 8 + (lane & 7);
        const int lcol = warp * 16 + ((lane >> 3) & 1) * 8;
#pragma unroll
        for (int ks = 0; ks < 2; ks++)
            ldsm_x4_t(qf[ks], smem_u32(&Qst[(ks * 16 + lrow) * 136 + lcol]));
        __syncthreads();
    }

    float m2[2] = {-1e30f, -1e30f}, l2[2] = {0.f, 0.f};
    float o[4][4];
#pragma unroll
    for (int nt = 0; nt < 4; nt++)
#pragma unroll
        for (int e = 0; e < 4; e++) o[nt][e] = 0.f;

    for (int ic = 0; ic < 4; ic++) {
        const int jt = ic * 64;
        const int sl = ic & 1;
        if (ic + 1 < 4) {
            const size_t kb = base + koff + (size_t)cd * HWP + jt + 64 + cj;
            CP_CG(smem_u32(&KV[sl ^ 1][0][cd][cj]), qv + kb);
            CP_CG(smem_u32(&KV[sl ^ 1][1][cd][cj]), qv + kb + koff);
            CP_COMMIT();
            CP_WAIT1();
        } else {
            CP_WAIT0();
        }
        __syncthreads();

        float s[8][4];
#pragma unroll
        for (int nt = 0; nt < 8; nt++)
#pragma unroll
            for (int e = 0; e < 4; e++) s[nt][e] = 0.f;
        const int krow = lane & 15;
#pragma unroll
        for (int ks = 0; ks < 2; ks++) {
            const uint32_t kb0 = smem_u32(&KV[sl][0][ks * 16 + krow][0]);
#pragma unroll
            for (int nt = 0; nt < 8; nt++) {
                uint32_t h0, h1;
                ldsm_x2_t(h0, h1, kb0 + nt * 16);
                mma16816h(s[nt], qf[ks], h0, h1);
            }
        }

        float mx[2] = {m2[0], m2[1]};
        const int i0 = qh * 128 + warp * 16 + gq;
#pragma unroll
        for (int nt = 0; nt < 8; nt++) {
            const int jb = jt + nt * 8 + 2 * tg;
#pragma unroll
            for (int e = 0; e < 4; e++) {
                const int i = i0 + (e >> 1) * 8;
                const int j = jb + (e & 1);
                const float t = fmaf(s[nt][e], scale2, bsh[i - j + 255]);
                s[nt][e] = t;
                mx[e >> 1] = fmaxf(mx[e >> 1], t);
            }
        }
#pragma unroll
        for (int slx = 0; slx < 2; slx++) {
            float v = mx[slx];
            v = fmaxf(v, __shfl_xor_sync(0xFFFFFFFFu, v, 1));
            v = fmaxf(v, __shfl_xor_sync(0xFFFFFFFFu, v, 2));
            mx[slx] = v;
        }
        float cf[2];
#pragma unroll
        for (int slx = 0; slx < 2; slx++) {
            cf[slx] = exp2f(m2[slx] - mx[slx]);
            m2[slx] = mx[slx];
            l2[slx] *= cf[slx];
        }
#pragma unroll
        for (int nt = 0; nt < 4; nt++)
#pragma unroll
            for (int e = 0; e < 4; e++) o[nt][e] *= cf[e >> 1];

        float rs[2] = {0.f, 0.f};
#pragma unroll
        for (int kp = 0; kp < 4; kp++) {
            uint32_t pf[4];
#pragma unroll
            for (int h2 = 0; h2 < 2; h2++) {
                const int nt = 2 * kp + h2;
                float p0 = exp2f(s[nt][0] - m2[0]);
                float p1 = exp2f(s[nt][1] - m2[0]);
                float p2 = exp2f(s[nt][2] - m2[1]);
                float p3 = exp2f(s[nt][3] - m2[1]);
                rs[0] += p0 + p1;
                rs[1] += p2 + p3;
                pf[h2 * 2 + 0] = pack_h2(__float2half(p0), __float2half(p1));
                pf[h2 * 2 + 1] = pack_h2(__float2half(p2), __float2half(p3));
            }
            const int vr = lane & 7, vk = kp * 16 + ((lane >> 3) & 1) * 8;
#pragma unroll
            for (int ntv = 0; ntv < 4; ntv++) {
                uint32_t v0, v1;
                ldsm_x2(v0, v1, smem_u32(&KV[sl][1][ntv * 8 + vr][vk]));
                mma16816h(o[ntv], pf, v0, v1);
            }
        }
#pragma unroll
        for (int slx = 0; slx < 2; slx++) {
            float r = rs[slx];
            r += __shfl_xor_sync(0xFFFFFFFFu, r, 1);
            r += __shfl_xor_sync(0xFFFFFFFFu, r, 2);
            l2[slx] += r;
        }
        __syncthreads();
    }

    const float inv0 = 1.f / l2[0], inv1 = 1.f / l2[1];
#pragma unroll
    for (int nt = 0; nt < 4; nt++) {
        const int c = nt * 8 + 2 * tg;
#pragma unroll
        for (int e = 0; e < 4; e++) {
            const int rr = warp * 16 + gq + (e >> 1) * 8;
            stage[rr * 33 + c + (e & 1)] = o[nt][e] * ((e >> 1) ? inv1 : inv0);
        }
    }
    __syncthreads();
    const size_t obase = (((size_t)b * CC + head * 32) * HH + row) * WW + qh * 128;
    const int q = tid & 127, db = (tid >> 7) * 16;
#pragma unroll
    for (int dd = 0; dd < 16; dd++) {
        const int d = db + dd;
        oa[obase + (size_t)d * HWP + q] = __float2half(stage[q * 33 + d]);
    }
}

// ---------------- launch ------------------------------------------------------
extern "C" void kernel_launch(void* const* d_in, const int* in_sizes, int n_in,
                              void* d_out, int out_size)
{
    const float* x       = (const float*)d_in[0];
    const float* rpb     = (const float*)d_in[1];
    const float* w_qkv   = (const float*)d_in[2];
    const float* w_depth = (const float*)d_in[3];
    const float* w_pre   = (const float*)d_in[4];
    const float* w_out   = (const float*)d_in[5];
    const float* w_gate  = (const float*)d_in[6];
    float* out = (float*)d_out;
    (void)in_sizes; (void)n_in; (void)out_size;

    float* gate;
    __half *th, *qv, *xh, *ah, *yh, *whi, *wlo;
    cudaGetSymbolAddress((void**)&gate, g_gate);
    cudaGetSymbolAddress((void**)&th,   g_t);
    cudaGetSymbolAddress((void**)&qv,   g_qv);
    cudaGetSymbolAddress((void**)&xh,   g_xh);
    cudaGetSymbolAddress((void**)&ah,   g_ah);
    cudaGetSymbolAddress((void**)&yh,   g_yh);
    cudaGetSymbolAddress((void**)&whi,  g_whi);
    cudaGetSymbolAddress((void**)&wlo,  g_wlo);

    cudaFuncSetAttribute(gemm_ar_kernel,
                         cudaFuncAttributeMaxDynamicSharedMemorySize, GSMEM);

    const int WS = CC * CC;
    const int nx = NB * CC * HWP;
    cvt4_kernel<<<(nx / 4 + 255) / 256, 256>>>(x, xh, nx / 4);
    wsplit_kernel<<<216, 256>>>(w_qkv, w_gate, w_pre, w_out, whi, wlo);

    const dim3 gMerged(HWP / (64 * NSUP), 8, NB);   // (128, 8, 2) = 2048 blocks
    const dim3 gSmall(HWP / (64 * NSUP), 2, NB);    // (128, 2, 2) = 512 blocks

    // [t | gate] = [W_qkv; W_gate] @ x
    gemm_ar_kernel<<<gMerged, 256, GSMEM>>>(whi, wlo, xh,
                                            nullptr, gate, th, 3 * CC, 3);
    // q,k,v = depthwise3x3(t) -> fp16
    dw_kernel<<<dim3(HH / 32, NB * 3 * CC), 256>>>(th, w_depth, qv);
    // attention -> fp16
    attn_mma_kernel<<<dim3(HH, 12, NB), 256>>>(qv, rpb, ah);
    // y = (W_pre @ attn) * gate -> fp16
    gemm_ar_kernel<<<gSmall, 256, GSMEM>>>(whi + 4 * WS, wlo + 4 * WS, ah,
                                           nullptr, gate, yh, CC, 2);
    // out = W_out @ y
    gemm_ar_kernel<<<gSmall, 256, GSMEM>>>(whi + 5 * WS, wlo + 5 * WS, yh,
                                           out, nullptr, nullptr, CC, 0);
}

// round 17
// speedup vs baseline: 1.1825x; 1.0100x over previous
#include <cuda_runtime.h>
#include <cuda_bf16.h>
#include <cuda_fp16.h>
#include <math.h>
#include <stdint.h>

#define HH 128
#define WW 256
#define CC 192
#define HWP (128*256)
#define NB 2
#define LOG2E 1.4426950408889634f

// ---------------- scratch (device globals) ----------------------------------
__device__ float g_gate[NB * CC * HWP];
__device__ __half g_t[NB * 3 * CC * HWP];      // qkv pre-dw, fp16
__device__ __half g_qv[NB * 3 * CC * HWP];     // q,k,v fp16 (dw output)
__device__ __half g_xh[NB * CC * HWP];         // x fp16
__device__ __half g_ah[NB * CC * HWP];         // attn out fp16
__device__ __half g_yh[NB * CC * HWP];         // pre*gate fp16
__device__ __half g_whi[6 * CC * CC];          // [qkv|gate|pre|out]
__device__ __half g_wlo[6 * CC * CC];

// ---------------- helpers -----------------------------------------------------
__device__ __forceinline__ uint32_t smem_u32(const void* p) {
    uint32_t a;
    asm("{ .reg .u64 t; cvta.to.shared.u64 t, %1; cvt.u32.u64 %0, t; }" : "=r"(a) : "l"(p));
    return a;
}
__device__ __forceinline__ void mma16816h(float* c, const uint32_t* a,
                                          uint32_t b0, uint32_t b1)
{
    asm volatile(
        "mma.sync.aligned.m16n8k16.row.col.f32.f16.f16.f32 "
        "{%0,%1,%2,%3}, {%4,%5,%6,%7}, {%8,%9}, {%0,%1,%2,%3};\n"
        : "+f"(c[0]), "+f"(c[1]), "+f"(c[2]), "+f"(c[3])
        : "r"(a[0]), "r"(a[1]), "r"(a[2]), "r"(a[3]), "r"(b0), "r"(b1));
}
__device__ __forceinline__ void ldsm_x4(uint32_t* d, uint32_t a) {
    asm volatile("ldmatrix.sync.aligned.m8n8.x4.shared.b16 {%0,%1,%2,%3}, [%4];\n"
                 : "=r"(d[0]), "=r"(d[1]), "=r"(d[2]), "=r"(d[3]) : "r"(a));
}
__device__ __forceinline__ void ldsm_x4_t(uint32_t* d, uint32_t a) {
    asm volatile("ldmatrix.sync.aligned.m8n8.x4.trans.shared.b16 {%0,%1,%2,%3}, [%4];\n"
                 : "=r"(d[0]), "=r"(d[1]), "=r"(d[2]), "=r"(d[3]) : "r"(a));
}
__device__ __forceinline__ void ldsm_x2(uint32_t& d0, uint32_t& d1, uint32_t a) {
    asm volatile("ldmatrix.sync.aligned.m8n8.x2.shared.b16 {%0,%1}, [%2];\n"
                 : "=r"(d0), "=r"(d1) : "r"(a));
}
__device__ __forceinline__ void ldsm_x2_t(uint32_t& d0, uint32_t& d1, uint32_t a) {
    asm volatile("ldmatrix.sync.aligned.m8n8.x2.trans.shared.b16 {%0,%1}, [%2];\n"
                 : "=r"(d0), "=r"(d1) : "r"(a));
}
__device__ __forceinline__ uint32_t pack_h2(__half a, __half b) {
    __half2 t = __halves2half2(a, b);
    return *(uint32_t*)&t;
}
#define CP_CA(d, s) asm volatile("cp.async.ca.shared.global [%0], [%1], 16;\n" :: "r"(d), "l"(s))
#define CP_CG(d, s) asm volatile("cp.async.cg.shared.global [%0], [%1], 16;\n" :: "r"(d), "l"(s))
#define CP_COMMIT() asm volatile("cp.async.commit_group;\n" ::: "memory")
#define CP_WAIT2()  asm volatile("cp.async.wait_group 2;\n" ::: "memory")
#define CP_WAIT1()  asm volatile("cp.async.wait_group 1;\n" ::: "memory")
#define CP_WAIT0()  asm volatile("cp.async.wait_group 0;\n" ::: "memory")

// ---------------- fp32 -> fp16, 4/thread -------------------------------------
__global__ void __launch_bounds__(256) cvt4_kernel(
    const float* __restrict__ x, __half* __restrict__ h, int n4)
{
    int i = blockIdx.x * 256 + threadIdx.x;
    if (i < n4) {
        float4 v = ((const float4*)x)[i];
        __half hh[4] = {__float2half(v.x), __float2half(v.y),
                        __float2half(v.z), __float2half(v.w)};
        ((uint2*)h)[i] = *(uint2*)hh;
    }
}

// ---------------- fused weight splits ([qkv|gate|pre|out], fp16 hi/lo) -------
__global__ void __launch_bounds__(256) wsplit_kernel(
    const float* __restrict__ wq, const float* __restrict__ wg,
    const float* __restrict__ wp, const float* __restrict__ wo,
    __half* __restrict__ hi, __half* __restrict__ lo)
{
    const int id = blockIdx.x;
    const float* src;
    size_t dbase;
    int local;
    if (id < 108)      { src = wq; local = id;       dbase = 0; }
    else if (id < 144) { src = wg; local = id - 108; dbase = (size_t)3 * CC * CC; }
    else if (id < 180) { src = wp; local = id - 144; dbase = (size_t)4 * CC * CC; }
    else               { src = wo; local = id - 180; dbase = (size_t)5 * CC * CC; }
    const int i = local * 256 + threadIdx.x;
    float4 v = ((const float4*)src)[i];
    float vs[4] = {v.x, v.y, v.z, v.w};
    __half h[4], l[4];
#pragma unroll
    for (int j = 0; j < 4; j++) {
        h[j] = __float2half(vs[j]);
        l[j] = __float2half(vs[j] - __half2float(h[j]));
    }
    ((uint2*)(hi + dbase))[i] = *(uint2*)h;
    ((uint2*)(lo + dbase))[i] = *(uint2*)l;
}

// ---------------- A-resident fp16 GEMM (templated n-supertile) ---------------
// BM=96 (full-K A resident), BN=64 x NSUP tiles; 8 warps = 2m(48) x 4n(16).
#define AR_HALF 38400
#define AR_BYTES 76800
#define BR_SLOT 2304
#define GSMEM (AR_BYTES + 4 * BR_SLOT)   // 86016

template <int NS>
__global__ void __launch_bounds__(256, 2) gemm_ar_kernel(
    const __half* __restrict__ Whi, const __half* __restrict__ Wlo,
    const __half* __restrict__ Xh,
    float* __restrict__ Yf, float* __restrict__ G,
    __half* __restrict__ Yh, int M, int epi)
{
    extern __shared__ __align__(16) char dsm[];
    const uint32_t sb = smem_u32(dsm);

    const int b  = blockIdx.z;
    const int m0 = blockIdx.y * 96;
    const int n0b = blockIdx.x * (64 * NS);
    const size_t xoff = (size_t)b * CC * HWP;

    const int tid  = threadIdx.x;
    const int lane = tid & 31;
    const int warp = tid >> 5;
    const int wm   = (warp >> 2) * 48;
    const int wn   = (warp & 3) * 16;
    const int gq   = lane >> 2;
    const int tg   = lane & 3;

    const int doB = (tid < 128);
    const int bk = (tid & 127) >> 3, bnc = (tid & 7) * 8;
    const uint32_t boff = (uint32_t)(bk * 144 + bnc * 2);

    // one-time A load + B prologue
    for (int u = tid; u < 4608; u += 256) {
        const int hh = (u >= 2304);
        const int v = u - hh * 2304;
        const int r = v / 24, c = v - r * 24;
        CP_CA(sb + hh * AR_HALF + (uint32_t)(r * 400 + c * 16),
              (hh ? Wlo : Whi) + (size_t)(m0 + r) * CC + c * 8);
    }
    const int TOT = NS * 12;
    if (doB) CP_CG(sb + AR_BYTES + 0 * BR_SLOT + boff,
                   Xh + xoff + (size_t)bk * HWP + n0b + bnc);
    CP_COMMIT();
#pragma unroll
    for (int s = 1; s < 3; s++) {
        if (doB) CP_CG(sb + AR_BYTES + s * BR_SLOT + boff,
                       Xh + xoff + (size_t)(s * 16 + bk) * HWP + n0b + bnc);
        CP_COMMIT();
    }

    float acc[3][2][4];
#pragma unroll
    for (int mt = 0; mt < 3; mt++)
#pragma unroll
        for (int nt = 0; nt < 2; nt++)
#pragma unroll
            for (int e = 0; e < 4; e++) acc[mt][nt][e] = 0.f;

    const size_t yoff = (size_t)b * M * HWP;
    const size_t goff = (size_t)b * CC * HWP;
    const int gateBlk = (epi == 3 && m0 >= 576);

    int tile = 0, k = 0;
    int ptile = 0, pk = 3;
    for (int g = 0; g < TOT; g++) {
        CP_WAIT2();
        __syncthreads();
        if (g + 3 < TOT) {
            if (doB) CP_CG(sb + AR_BYTES + (uint32_t)((g + 3) & 3) * BR_SLOT + boff,
                           Xh + xoff + (size_t)(pk * 16 + bk) * HWP
                              + n0b + ptile * 64 + bnc);
            if (++pk == 12) { pk = 0; ptile++; }
        }
        CP_COMMIT();

        const uint32_t Bs = sb + AR_BYTES + (uint32_t)(g & 3) * BR_SLOT;
        uint32_t bf[2][2];
        {
            const uint32_t brow = (uint32_t)(lane & 15) * 144 + (uint32_t)wn * 2;
#pragma unroll
            for (int nt = 0; nt < 2; nt++)
                ldsm_x2_t(bf[nt][0], bf[nt][1], Bs + brow + nt * 16);
        }
#pragma unroll
        for (int mt = 0; mt < 3; mt++) {
            uint32_t afh[4], afl[4];
            const uint32_t arow = (uint32_t)(wm + mt * 16 + (lane & 15)) * 400
                                + (uint32_t)(k * 32 + (lane >> 4) * 16);
            ldsm_x4(afh, sb + arow);
            ldsm_x4(afl, sb + AR_HALF + arow);
#pragma unroll
            for (int nt = 0; nt < 2; nt++) {
                mma16816h(acc[mt][nt], afh, bf[nt][0], bf[nt][1]);
                mma16816h(acc[mt][nt], afl, bf[nt][0], bf[nt][1]);
            }
        }

        if (++k == 12) {
            const int n0 = n0b + tile * 64;
#pragma unroll
            for (int mt = 0; mt < 3; mt++) {
                const int r0 = m0 + wm + mt * 16 + gq;
                const int r1 = r0 + 8;
#pragma unroll
                for (int nt = 0; nt < 2; nt++) {
                    const int c = n0 + wn + nt * 8 + 2 * tg;
                    float v00 = acc[mt][nt][0], v01 = acc[mt][nt][1];
                    float v10 = acc[mt][nt][2], v11 = acc[mt][nt][3];
                    if (gateBlk) {
                        v00 = v00 / (1.f + __expf(-v00));
                        v01 = v01 / (1.f + __expf(-v01));
                        v10 = v10 / (1.f + __expf(-v10));
                        v11 = v11 / (1.f + __expf(-v11));
                        *(float2*)(G + goff + (size_t)(r0 - 576) * HWP + c) =
                            make_float2(v00, v01);
                        *(float2*)(G + goff + (size_t)(r1 - 576) * HWP + c) =
                            make_float2(v10, v11);
                    } else if (epi == 3) {
                        *(uint32_t*)(Yh + yoff + (size_t)r0 * HWP + c) =
                            pack_h2(__float2half(v00), __float2half(v01));
                        *(uint32_t*)(Yh + yoff + (size_t)r1 * HWP + c) =
                            pack_h2(__float2half(v10), __float2half(v11));
                    } else if (epi == 2) {
                        float2 g0 = *(const float2*)(G + goff + (size_t)r0 * HWP + c);
                        float2 g1 = *(const float2*)(G + goff + (size_t)r1 * HWP + c);
                        v00 *= g0.x; v01 *= g0.y; v10 *= g1.x; v11 *= g1.y;
                        *(uint32_t*)(Yh + yoff + (size_t)r0 * HWP + c) =
                            pack_h2(__float2half(v00), __float2half(v01));
                        *(uint32_t*)(Yh + yoff + (size_t)r1 * HWP + c) =
                            pack_h2(__float2half(v10), __float2half(v11));
                    } else {
                        *(float2*)(Yf + yoff + (size_t)r0 * HWP + c) =
                            make_float2(v00, v01);
                        *(float2*)(Yf + yoff + (size_t)r1 * HWP + c) =
                            make_float2(v10, v11);
                    }
                    acc[mt][nt][0] = 0.f; acc[mt][nt][1] = 0.f;
                    acc[mt][nt][2] = 0.f; acc[mt][nt][3] = 0.f;
                }
            }
            k = 0;
            tile++;
        }
    }
}

// ---------------- depthwise 3x3, 4x8 patch/thread, half2 converts ------------
__global__ void __launch_bounds__(256) dw_kernel(
    const __half* __restrict__ t, const float* __restrict__ wd,
    __half* __restrict__ oh)
{
    const int cb = blockIdx.y;
    const int c  = cb % (3 * CC);
    const int tx = threadIdx.x;
    const int x  = (tx & 31) * 8;
    const int yq = blockIdx.x * 32 + (tx >> 5) * 4;
    const __half* base = t + (size_t)cb * HWP;

    float w[9];
#pragma unroll
    for (int i = 0; i < 9; i++) w[i] = wd[c * 9 + i];

    float acc[4][8];
#pragma unroll
    for (int o = 0; o < 4; o++)
#pragma unroll
        for (int i = 0; i < 8; i++) acc[o][i] = 0.f;

#pragma unroll
    for (int ry = -1; ry <= 4; ry++) {
        const int yy = yq + ry;
        if (yy < 0 || yy >= HH) continue;
        const __half* r = base + yy * WW + x;
        uint4 u = *(const uint4*)r;
        __half2 hv2[4];
        *(uint4*)hv2 = u;
        float v[10];
        v[0] = (x > 0) ? __half2float(r[-1]) : 0.f;
#pragma unroll
        for (int i = 0; i < 4; i++) {
            float2 f = __half22float2(hv2[i]);
            v[i * 2 + 1] = f.x;
            v[i * 2 + 2] = f.y;
        }
        v[9] = (x < 248) ? __half2float(r[8]) : 0.f;
#pragma unroll
        for (int o = 0; o < 4; o++) {
            const int d = ry - o;
            if (d < -1 || d > 1) continue;
            const int wr = (d + 1) * 3;
#pragma unroll
            for (int i = 0; i < 8; i++)
                acc[o][i] = fmaf(w[wr], v[i],
                            fmaf(w[wr + 1], v[i + 1],
                            fmaf(w[wr + 2], v[i + 2], acc[o][i])));
        }
    }
#pragma unroll
    for (int o = 0; o < 4; o++) {
        __half h[8];
#pragma unroll
        for (int i = 0; i < 8; i++) h[i] = __float2half(acc[o][i]);
        *(uint4*)(oh + (size_t)cb * HWP + (yq + o) * WW + x) = *(uint4*)h;
    }
}

// ---------------- attention (R11: 256 thr, 2 CTA/SM, cp.async dbuf) ----------
__global__ void __launch_bounds__(256, 2) attn_mma_kernel(
    const __half* __restrict__ qv, const float* __restrict__ rpb,
    __half* __restrict__ oa)
{
    __shared__ float bsh[512];
    __shared__ __align__(16) __half KV[2][2][32][72];
    __shared__ __align__(16) float stage[128 * 33];

    const int row = blockIdx.x;
    const int head = blockIdx.y % 6, qh = blockIdx.y / 6;
    const int b = blockIdx.z;
    const int tid = threadIdx.x, lane = tid & 31, warp = tid >> 5;
    const int gq = lane >> 2, tg = lane & 3;
    const size_t base = (((size_t)b * (3 * CC) + head * 32) * HH + row) * WW;
    const size_t koff = (size_t)CC * HWP;
    const float scale2 = 0.17677669529663687f * LOG2E;

    const int cd = tid >> 3, cj = (tid & 7) * 8;
    {
        const size_t kb = base + koff + (size_t)cd * HWP + 0 + cj;
        CP_CG(smem_u32(&KV[0][0][cd][cj]), qv + kb);
        CP_CG(smem_u32(&KV[0][1][cd][cj]), qv + kb + koff);
        CP_COMMIT();
    }

    for (int i = tid; i < 511; i += 256) bsh[i] = rpb[i * 6 + head] * LOG2E;

    uint32_t qf[2][4];
    {
        __half* Qst = (__half*)stage;
        const int d = tid >> 3, q16 = (tid & 7) * 16;
        const size_t go = base + (size_t)d * HWP + qh * 128 + q16;
        uint4 v0 = *(const uint4*)(qv + go);
        uint4 v1 = *(const uint4*)(qv + go + 8);
        *(uint4*)&Qst[d * 136 + q16] = v0;
        *(uint4*)&Qst[d * 136 + q16 + 8] = v1;
        __syncthreads();
        const int lrow = ((lane >> 4) & 1) * 8 + (lane & 7);
        const int lcol = warp * 16 + ((lane >> 3) & 1) * 8;
#pragma unroll
        for (int ks = 0; ks < 2; ks++)
            ldsm_x4_t(qf[ks], smem_u32(&Qst[(ks * 16 + lrow) * 136 + lcol]));
        __syncthreads();
    }

    float m2[2] = {-1e30f, -1e30f}, l2[2] = {0.f, 0.f};
    float o[4][4];
#pragma unroll
    for (int nt = 0; nt < 4; nt++)
#pragma unroll
        for (int e = 0; e < 4; e++) o[nt][e] = 0.f;

    for (int ic = 0; ic < 4; ic++) {
        const int jt = ic * 64;
        const int sl = ic & 1;
        if (ic + 1 < 4) {
            const size_t kb = base + koff + (size_t)cd * HWP + jt + 64 + cj;
            CP_CG(smem_u32(&KV[sl ^ 1][0][cd][cj]), qv + kb);
            CP_CG(smem_u32(&KV[sl ^ 1][1][cd][cj]), qv + kb + koff);
            CP_COMMIT();
            CP_WAIT1();
        } else {
            CP_WAIT0();
        }
        __syncthreads();

        float s[8][4];
#pragma unroll
        for (int nt = 0; nt < 8; nt++)
#pragma unroll
            for (int e = 0; e < 4; e++) s[nt][e] = 0.f;
        const int krow = lane & 15;
#pragma unroll
        for (int ks = 0; ks < 2; ks++) {
            const uint32_t kb0 = smem_u32(&KV[sl][0][ks * 16 + krow][0]);
#pragma unroll
            for (int nt = 0; nt < 8; nt++) {
                uint32_t h0, h1;
                ldsm_x2_t(h0, h1, kb0 + nt * 16);
                mma16816h(s[nt], qf[ks], h0, h1);
            }
        }

        float mx[2] = {m2[0], m2[1]};
        const int i0 = qh * 128 + warp * 16 + gq;
#pragma unroll
        for (int nt = 0; nt < 8; nt++) {
            const int jb = jt + nt * 8 + 2 * tg;
#pragma unroll
            for (int e = 0; e < 4; e++) {
                const int i = i0 + (e >> 1) * 8;
                const int j = jb + (e & 1);
                const float t = fmaf(s[nt][e], scale2, bsh[i - j + 255]);
                s[nt][e] = t;
                mx[e >> 1] = fmaxf(mx[e >> 1], t);
            }
        }
#pragma unroll
        for (int slx = 0; slx < 2; slx++) {
            float v = mx[slx];
            v = fmaxf(v, __shfl_xor_sync(0xFFFFFFFFu, v, 1));
            v = fmaxf(v, __shfl_xor_sync(0xFFFFFFFFu, v, 2));
            mx[slx] = v;
        }
        float cf[2];
#pragma unroll
        for (int slx = 0; slx < 2; slx++) {
            cf[slx] = exp2f(m2[slx] - mx[slx]);
            m2[slx] = mx[slx];
            l2[slx] *= cf[slx];
        }
#pragma unroll
        for (int nt = 0; nt < 4; nt++)
#pragma unroll
            for (int e = 0; e < 4; e++) o[nt][e] *= cf[e >> 1];

        float rs[2] = {0.f, 0.f};
#pragma unroll
        for (int kp = 0; kp < 4; kp++) {
            uint32_t pf[4];
#pragma unroll
            for (int h2 = 0; h2 < 2; h2++) {
                const int nt = 2 * kp + h2;
                float p0 = exp2f(s[nt][0] - m2[0]);
                float p1 = exp2f(s[nt][1] - m2[0]);
                float p2 = exp2f(s[nt][2] - m2[1]);
                float p3 = exp2f(s[nt][3] - m2[1]);
                rs[0] += p0 + p1;
                rs[1] += p2 + p3;
                pf[h2 * 2 + 0] = pack_h2(__float2half(p0), __float2half(p1));
                pf[h2 * 2 + 1] = pack_h2(__float2half(p2), __float2half(p3));
            }
            const int vr = lane & 7, vk = kp * 16 + ((lane >> 3) & 1) * 8;
#pragma unroll
            for (int ntv = 0; ntv < 4; ntv++) {
                uint32_t v0, v1;
                ldsm_x2(v0, v1, smem_u32(&KV[sl][1][ntv * 8 + vr][vk]));
                mma16816h(o[ntv], pf, v0, v1);
            }
        }
#pragma unroll
        for (int slx = 0; slx < 2; slx++) {
            float r = rs[slx];
            r += __shfl_xor_sync(0xFFFFFFFFu, r, 1);
            r += __shfl_xor_sync(0xFFFFFFFFu, r, 2);
            l2[slx] += r;
        }
        __syncthreads();
    }

    const float inv0 = 1.f / l2[0], inv1 = 1.f / l2[1];
#pragma unroll
    for (int nt = 0; nt < 4; nt++) {
        const int c = nt * 8 + 2 * tg;
#pragma unroll
        for (int e = 0; e < 4; e++) {
            const int rr = warp * 16 + gq + (e >> 1) * 8;
            stage[rr * 33 + c + (e & 1)] = o[nt][e] * ((e >> 1) ? inv1 : inv0);
        }
    }
    __syncthreads();
    const size_t obase = (((size_t)b * CC + head * 32) * HH + row) * WW + qh * 128;
    const int q = tid & 127, db = (tid >> 7) * 16;
#pragma unroll
    for (int dd = 0; dd < 16; dd++) {
        const int d = db + dd;
        oa[obase + (size_t)d * HWP + q] = __float2half(stage[q * 33 + d]);
    }
}

// ---------------- launch ------------------------------------------------------
extern "C" void kernel_launch(void* const* d_in, const int* in_sizes, int n_in,
                              void* d_out, int out_size)
{
    const float* x       = (const float*)d_in[0];
    const float* rpb     = (const float*)d_in[1];
    const float* w_qkv   = (const float*)d_in[2];
    const float* w_depth = (const float*)d_in[3];
    const float* w_pre   = (const float*)d_in[4];
    const float* w_out   = (const float*)d_in[5];
    const float* w_gate  = (const float*)d_in[6];
    float* out = (float*)d_out;
    (void)in_sizes; (void)n_in; (void)out_size;

    float* gate;
    __half *th, *qv, *xh, *ah, *yh, *whi, *wlo;
    cudaGetSymbolAddress((void**)&gate, g_gate);
    cudaGetSymbolAddress((void**)&th,   g_t);
    cudaGetSymbolAddress((void**)&qv,   g_qv);
    cudaGetSymbolAddress((void**)&xh,   g_xh);
    cudaGetSymbolAddress((void**)&ah,   g_ah);
    cudaGetSymbolAddress((void**)&yh,   g_yh);
    cudaGetSymbolAddress((void**)&whi,  g_whi);
    cudaGetSymbolAddress((void**)&wlo,  g_wlo);

    cudaFuncSetAttribute(gemm_ar_kernel<4>,
                         cudaFuncAttributeMaxDynamicSharedMemorySize, GSMEM);
    cudaFuncSetAttribute(gemm_ar_kernel<8>,
                         cudaFuncAttributeMaxDynamicSharedMemorySize, GSMEM);

    const int WS = CC * CC;
    const int nx = NB * CC * HWP;
    cvt4_kernel<<<(nx / 4 + 255) / 256, 256>>>(x, xh, nx / 4);
    wsplit_kernel<<<216, 256>>>(w_qkv, w_gate, w_pre, w_out, whi, wlo);

    const dim3 gMerged(HWP / 256, 8, NB);    // NSUP=4: (128, 8, 2) = 2048 blocks
    const dim3 gSmall(HWP / 512, 2, NB);     // NSUP=8: (64, 2, 2) = 256 blocks

    // [t | gate] = [W_qkv; W_gate] @ x
    gemm_ar_kernel<4><<<gMerged, 256, GSMEM>>>(whi, wlo, xh,
                                               nullptr, gate, th, 3 * CC, 3);
    // q,k,v = depthwise3x3(t) -> fp16
    dw_kernel<<<dim3(HH / 32, NB * 3 * CC), 256>>>(th, w_depth, qv);
    // attention -> fp16
    attn_mma_kernel<<<dim3(HH, 12, NB), 256>>>(qv, rpb, ah);
    // y = (W_pre @ attn) * gate -> fp16
    gemm_ar_kernel<8><<<gSmall, 256, GSMEM>>>(whi + 4 * WS, wlo + 4 * WS, ah,
                                              nullptr, gate, yh, CC, 2);
    // out = W_out @ y
    gemm_ar_kernel<8><<<gSmall, 256, GSMEM>>>(whi + 5 * WS, wlo + 5 * WS, yh,
                                              out, nullptr, nullptr, CC, 0);
}